// round 14
// baseline (speedup 1.0000x reference)
#include <cuda_runtime.h>
#include <cuda_fp16.h>
#include <cstdint>

// ---------------------------------------------------------------------------
// Sparse 3D CNN pipeline. Round 14: conv is LSU-issue-bound (cp.async rt=8).
// Cut LSU ops: block 128x256 (512 thr, 16 warps, 2Mx8N), B fragments fetched
// by direct LDG.32 (no B smem/cp/ldmatrix), A via cp.async (1 op/thread/iter).
// v4 red scatter + center-split retained.
// ---------------------------------------------------------------------------

__device__ float  g_acc[32768 * 512];
__device__ __half g_hA[32768 * 512];
__device__ __half g_hB[32768 * 512];
__device__ __half g_wh[38928384];               // fp16 weights [27][512][ci]
__device__ float  g_sum[512];
__device__ float  g_sumsq[512];
__device__ float  g_coefA[512];
__device__ float  g_coefB[512];
__device__ int    g_cnt1[27];
__device__ int    g_cnt2[27];
__device__ float  g_glob[8 * 512];
__device__ float  g_fcb1[8 * 4096];
__device__ float  g_fcb2[8 * 4096];

#define BM 128
#define BN 256
#define BK 32
#define STAGES 4
#define ALDH 40

#define A_ST_H (BM * ALDH)
#define IDX_OFF (STAGES * A_ST_H)                 // halves; ints follow
#define SMEM_BYTES (IDX_OFF * 2 + 2 * BM * 4)

static __device__ __forceinline__ uint32_t smem_u32(const void* p) {
    uint32_t a;
    asm("{ .reg .u64 t; cvta.to.shared.u64 t, %1; cvt.u32.u64 %0, t; }"
        : "=r"(a) : "l"(p));
    return a;
}
static __device__ __forceinline__ void cp16(uint32_t dst, const void* src, bool v) {
    asm volatile("cp.async.cg.shared.global [%0], [%1], 16, %2;"
                 :: "r"(dst), "l"(src), "r"(v ? 16 : 0));
}
#define CP_COMMIT() asm volatile("cp.async.commit_group;" ::: "memory")
#define CP_WAIT2()  asm volatile("cp.async.wait_group 2;" ::: "memory")

static __device__ __forceinline__ void ldsm4(uint32_t& r0, uint32_t& r1,
                                             uint32_t& r2, uint32_t& r3,
                                             uint32_t addr) {
    asm volatile("ldmatrix.sync.aligned.m8n8.x4.shared.b16 {%0,%1,%2,%3}, [%4];"
                 : "=r"(r0), "=r"(r1), "=r"(r2), "=r"(r3) : "r"(addr));
}
static __device__ __forceinline__ void red4(float* p, float v0, float v1,
                                            float v2, float v3) {
    asm volatile("red.global.add.v4.f32 [%0], {%1,%2,%3,%4};"
                 :: "l"(p), "f"(v0), "f"(v1), "f"(v2), "f"(v3) : "memory");
}

// Shared mainloop body: A from smem via ldmatrix, B direct from gmem.
// wptr = &Wk[(wn*32 + lane/4)*K + (lane&3)*2]; K8 = 8*K (halves).
#define TILE_MMA_BDIR(Af, kit)                                                 \
    do {                                                                       \
        _Pragma("unroll")                                                      \
        for (int h = 0; h < 2; h++) {                                          \
            int kb = h * 16;                                                   \
            uint32_t b[4][2];                                                  \
            _Pragma("unroll")                                                  \
            for (int nt = 0; nt < 4; nt++) {                                   \
                b[nt][0] = *(const uint32_t*)(wptr + (long)nt * K8 + (kit) * 32 + kb);      \
                b[nt][1] = *(const uint32_t*)(wptr + (long)nt * K8 + (kit) * 32 + kb + 8);  \
            }                                                                  \
            _Pragma("unroll")                                                  \
            for (int mt = 0; mt < 4; mt++) {                                   \
                uint32_t a0, a1, a2, a3;                                       \
                int rowa = wm * 64 + mt * 16 + lr8 + (lg & 1) * 8;             \
                ldsm4(a0, a1, a2, a3,                                          \
                      (Af) + ((rowa * ALDH) + kb + (lg >> 1) * 8) * 2);        \
                _Pragma("unroll")                                              \
                for (int nt = 0; nt < 4; nt++) {                               \
                    asm volatile(                                              \
                        "mma.sync.aligned.m16n8k16.row.col.f32.f16.f16.f32 "   \
                        "{%0,%1,%2,%3}, {%4,%5,%6,%7}, {%8,%9}, {%0,%1,%2,%3};"\
                        : "+f"(acc[mt][nt][0]), "+f"(acc[mt][nt][1]),          \
                          "+f"(acc[mt][nt][2]), "+f"(acc[mt][nt][3])           \
                        : "r"(a0), "r"(a1), "r"(a2), "r"(a3),                  \
                          "r"(b[nt][0]), "r"(b[nt][1]));                       \
                }                                                              \
            }                                                                  \
        }                                                                      \
    } while (0)

__global__ void k_count(const int* __restrict__ out_idx, int P, int sentinel,
                        int* __restrict__ counts) {
    int k = blockIdx.x;
    const int* o = out_idx + (long)k * P;
    int c = 0;
    for (int p = threadIdx.x; p < P; p += blockDim.x) c += (o[p] != sentinel);
    __shared__ int sm[256];
    sm[threadIdx.x] = c;
    __syncthreads();
    for (int s = 128; s > 0; s >>= 1) {
        if (threadIdx.x < s) sm[threadIdx.x] += sm[threadIdx.x + s];
        __syncthreads();
    }
    if (threadIdx.x == 0) counts[k] = sm[0];
}

// W[27][ci][512] f32 -> Wh[27][512][ci] half
__global__ void k_wt(const float* __restrict__ W, __half* __restrict__ out, int ci) {
    __shared__ float t[32][33];
    int k = blockIdx.z;
    int i0 = blockIdx.y * 32, o0 = blockIdx.x * 32;
    int tx = threadIdx.x, ty = threadIdx.y;
#pragma unroll
    for (int r = 0; r < 32; r += 8)
        t[ty + r][tx] = W[((long)k * ci + i0 + ty + r) * 512 + o0 + tx];
    __syncthreads();
#pragma unroll
    for (int r = 0; r < 32; r += 8)
        out[((long)k * 512 + o0 + ty + r) * ci + i0 + tx] = __float2half(t[tx][ty + r]);
}

__global__ void k_f2h(const float* __restrict__ x, __half* __restrict__ y, int n) {
    int i = blockIdx.x * blockDim.x + threadIdx.x;
    int stride = gridDim.x * blockDim.x;
    for (; i < n; i += stride) y[i] = __float2half(x[i]);
}

// ---------------------------------------------------------------------------
// Gather conv. 512 threads, block 128x256. blockIdx.z = offset (skip13 opt).
// ---------------------------------------------------------------------------
__global__ __launch_bounds__(512, 1)
void k_conv_off(const __half* __restrict__ x, const __half* __restrict__ Wh,
                const int* __restrict__ in_idx, const int* __restrict__ out_idx,
                const int* __restrict__ counts, int P, int K, int skip13,
                float* __restrict__ out) {
    int koff = blockIdx.z;
    if (skip13 && koff >= 13) koff++;
    int count = counts[koff];
    int row0 = blockIdx.x * BM;
    if (row0 >= count) return;
    int col0 = blockIdx.y * BN;
    const __half* Wk = Wh + (long)koff * 512 * K;

    extern __shared__ __half smh[];
    int* rs = (int*)(smh + IDX_OFF);
    int* os = rs + BM;

    int tid = threadIdx.x;
    if (tid < BM) {
        int p = row0 + tid;
        bool v = p < count;
        rs[tid] = v ? in_idx[(long)koff * P + p] : -1;
        os[tid] = v ? out_idx[(long)koff * P + p] : -1;
    }
    __syncthreads();

    // A loader: thread t -> row t>>2, 16B segment (t&3)
    int arow = tid >> 2;
    int aseg = (tid & 3) * 8;             // halves
    int ar = rs[arow];
    const __half* xrow = (ar >= 0) ? &x[(long)ar * K] : nullptr;

    uint32_t As_u = smem_u32(smh);
    auto issue_stage = [&](int stage, int k0) {
        uint32_t Ab = As_u + stage * A_ST_H * 2;
        const __half* asrc = xrow ? (xrow + k0 + aseg) : x;
        cp16(Ab + (arow * ALDH + aseg) * 2, asrc, xrow != nullptr);
        CP_COMMIT();
    };

    int warp = tid >> 5, lane = tid & 31;
    int wm = warp & 1;        // rows wm*64
    int wn = warp >> 1;       // cols wn*32 (0..7)
    int lg = lane >> 3, lr8 = lane & 7;

    long K8 = (long)K * 8;
    const __half* wptr = &Wk[(long)(col0 + wn * 32 + (lane >> 2)) * K + (lane & 3) * 2];

    float acc[4][4][4];
#pragma unroll
    for (int mt = 0; mt < 4; mt++)
#pragma unroll
        for (int nt = 0; nt < 4; nt++)
#pragma unroll
            for (int i = 0; i < 4; i++) acc[mt][nt][i] = 0.0f;

    int nIter = K / BK;
    issue_stage(0, 0);
    if (nIter > 1) issue_stage(1, BK);
    if (nIter > 2) issue_stage(2, 2 * BK);

    for (int it = 0; it < nIter; it++) {
        CP_WAIT2();
        __syncthreads();
        if (it + 3 < nIter) issue_stage((it + 3) % STAGES, (it + 3) * BK);

        uint32_t Af = As_u + (it % STAGES) * A_ST_H * 2;
        TILE_MMA_BDIR(Af, it);
    }

    // quad-shuffle epilogue, red.v4
    int lr = lane >> 2, lq = lane & 3;
    int odd = lane & 1;
#pragma unroll
    for (int mt = 0; mt < 4; mt++) {
        int rbase = wm * 64 + mt * 16 + lr;
        int o_lo = os[rbase];
        int o_hi = os[rbase + 8];
        int o = odd ? o_hi : o_lo;
#pragma unroll
        for (int nt = 0; nt < 4; nt++) {
            float e0 = __shfl_xor_sync(0xffffffffu, acc[mt][nt][0], 1);
            float e1 = __shfl_xor_sync(0xffffffffu, acc[mt][nt][1], 1);
            float e2 = __shfl_xor_sync(0xffffffffu, acc[mt][nt][2], 1);
            float e3 = __shfl_xor_sync(0xffffffffu, acc[mt][nt][3], 1);
            float v0, v1, v2, v3;
            if (!odd) { v0 = acc[mt][nt][0]; v1 = acc[mt][nt][1]; v2 = e0; v3 = e1; }
            else      { v0 = e2; v1 = e3; v2 = acc[mt][nt][2]; v3 = acc[mt][nt][3]; }
            int cb = col0 + wn * 32 + nt * 8 + (lq & 2) * 2;
            if (o >= 0) red4(&out[(long)o * 512 + cb], v0, v1, v2, v3);
        }
    }
}

// ---------------------------------------------------------------------------
// Center offset: identity map, dense rows, plain v4 stores (initializes out).
// ---------------------------------------------------------------------------
__global__ __launch_bounds__(512, 1)
void k_conv_center(const __half* __restrict__ x, const __half* __restrict__ W13,
                   int n, int K, float* __restrict__ out) {
    int row0 = blockIdx.x * BM;
    int col0 = blockIdx.y * BN;

    extern __shared__ __half smh[];
    int tid = threadIdx.x;
    int arow = tid >> 2;
    int aseg = (tid & 3) * 8;
    int grow = row0 + arow;
    const __half* xrow = (grow < n) ? &x[(long)grow * K] : nullptr;

    uint32_t As_u = smem_u32(smh);
    auto issue_stage = [&](int stage, int k0) {
        uint32_t Ab = As_u + stage * A_ST_H * 2;
        const __half* asrc = xrow ? (xrow + k0 + aseg) : x;
        cp16(Ab + (arow * ALDH + aseg) * 2, asrc, xrow != nullptr);
        CP_COMMIT();
    };

    int warp = tid >> 5, lane = tid & 31;
    int wm = warp & 1, wn = warp >> 1;
    int lg = lane >> 3, lr8 = lane & 7;

    long K8 = (long)K * 8;
    const __half* wptr = &W13[(long)(col0 + wn * 32 + (lane >> 2)) * K + (lane & 3) * 2];

    float acc[4][4][4];
#pragma unroll
    for (int mt = 0; mt < 4; mt++)
#pragma unroll
        for (int nt = 0; nt < 4; nt++)
#pragma unroll
            for (int i = 0; i < 4; i++) acc[mt][nt][i] = 0.0f;

    int nIter = K / BK;
    issue_stage(0, 0);
    if (nIter > 1) issue_stage(1, BK);
    if (nIter > 2) issue_stage(2, 2 * BK);

    for (int it = 0; it < nIter; it++) {
        CP_WAIT2();
        __syncthreads();
        if (it + 3 < nIter) issue_stage((it + 3) % STAGES, (it + 3) * BK);

        uint32_t Af = As_u + (it % STAGES) * A_ST_H * 2;
        TILE_MMA_BDIR(Af, it);
    }

    int lr = lane >> 2, lq = lane & 3;
    int odd = lane & 1;
#pragma unroll
    for (int mt = 0; mt < 4; mt++) {
        int r_lo = row0 + wm * 64 + mt * 16 + lr;
        int r = odd ? (r_lo + 8) : r_lo;
#pragma unroll
        for (int nt = 0; nt < 4; nt++) {
            float e0 = __shfl_xor_sync(0xffffffffu, acc[mt][nt][0], 1);
            float e1 = __shfl_xor_sync(0xffffffffu, acc[mt][nt][1], 1);
            float e2 = __shfl_xor_sync(0xffffffffu, acc[mt][nt][2], 1);
            float e3 = __shfl_xor_sync(0xffffffffu, acc[mt][nt][3], 1);
            float4 v;
            if (!odd) { v.x = acc[mt][nt][0]; v.y = acc[mt][nt][1]; v.z = e0; v.w = e1; }
            else      { v.x = e2; v.y = e3; v.z = acc[mt][nt][2]; v.w = acc[mt][nt][3]; }
            int cb = col0 + wn * 32 + nt * 8 + (lq & 2) * 2;
            if (r < n) *(float4*)&out[(long)r * 512 + cb] = v;
        }
    }
}

// ---------------------------------------------------------------------------
__global__ void k_bn_stats(const float* __restrict__ x, int n) {
    int c = threadIdx.x;
    int r0 = blockIdx.x * 128;
    int rend = min(r0 + 128, n);
    float s0 = 0.f, s20 = 0.f, s1 = 0.f, s21 = 0.f;
    for (int r = r0; r < rend; r++) {
        float v0 = x[(long)r * 512 + c];
        float v1 = x[(long)r * 512 + c + 256];
        s0 += v0; s20 += v0 * v0;
        s1 += v1; s21 += v1 * v1;
    }
    atomicAdd(&g_sum[c], s0);
    atomicAdd(&g_sumsq[c], s20);
    atomicAdd(&g_sum[c + 256], s1);
    atomicAdd(&g_sumsq[c + 256], s21);
}

__global__ void k_bn_coef(const float* __restrict__ gamma,
                          const float* __restrict__ beta, float inv_n) {
    int c = threadIdx.x;
    float mu = g_sum[c] * inv_n;
    float var = g_sumsq[c] * inv_n - mu * mu;
    float a = gamma[c] * rsqrtf(var + 1e-5f);
    g_coefA[c] = a;
    g_coefB[c] = beta[c] - mu * a;
    g_sum[c] = 0.0f;
    g_sumsq[c] = 0.0f;
}

__global__ void k_bn_apply_h(const float* __restrict__ x, __half* __restrict__ y,
                             int total8) {
    int i = blockIdx.x * blockDim.x + threadIdx.x;
    int stride = gridDim.x * blockDim.x;
    for (; i < total8; i += stride) {
        float4 v0 = ((const float4*)x)[i * 2];
        float4 v1 = ((const float4*)x)[i * 2 + 1];
        int c = (i * 8) & 511;
        float4 a0 = *(const float4*)&g_coefA[c];
        float4 a1 = *(const float4*)&g_coefA[c + 4];
        float4 b0 = *(const float4*)&g_coefB[c];
        float4 b1 = *(const float4*)&g_coefB[c + 4];
        __half2 h[4];
        h[0] = __floats2half2_rn(fmaxf(v0.x * a0.x + b0.x, 0.f), fmaxf(v0.y * a0.y + b0.y, 0.f));
        h[1] = __floats2half2_rn(fmaxf(v0.z * a0.z + b0.z, 0.f), fmaxf(v0.w * a0.w + b0.w, 0.f));
        h[2] = __floats2half2_rn(fmaxf(v1.x * a1.x + b1.x, 0.f), fmaxf(v1.y * a1.y + b1.y, 0.f));
        h[3] = __floats2half2_rn(fmaxf(v1.z * a1.z + b1.z, 0.f), fmaxf(v1.w * a1.w + b1.w, 0.f));
        ((uint4*)y)[i] = *(const uint4*)h;
    }
}

// ---------------------------------------------------------------------------
__global__ void k_pool_max_h(const __half* __restrict__ x, const int* __restrict__ idx,
                             float* __restrict__ out, int n_in) {
    long total = (long)n_in * 512;
    long i = (long)blockIdx.x * blockDim.x + threadIdx.x;
    long stride = (long)gridDim.x * blockDim.x;
    for (; i < total; i += stride) {
        int r = (int)(i >> 9);
        int c = (int)(i & 511);
        float v = __half2float(x[i]);
        atomicMax((int*)&out[(long)idx[r] * 512 + c], __float_as_int(v));
    }
}

__global__ void k_pool_max_f(const float* __restrict__ x, const int* __restrict__ idx,
                             float* __restrict__ out, int n_in) {
    long total = (long)n_in * 512;
    long i = (long)blockIdx.x * blockDim.x + threadIdx.x;
    long stride = (long)gridDim.x * blockDim.x;
    for (; i < total; i += stride) {
        int r = (int)(i >> 9);
        int c = (int)(i & 511);
        float v = x[i];
        atomicMax((int*)&out[(long)idx[r] * 512 + c], __float_as_int(v));
    }
}

// ---------------------------------------------------------------------------
__global__ __launch_bounds__(256)
void k_fc(const float* __restrict__ x, const float* __restrict__ w,
          const float* __restrict__ bias, float* __restrict__ y,
          int K, int N, int do_relu) {
    __shared__ float xs[8 * 512];
    __shared__ float red_[4][64][8];
    int tid = threadIdx.x;
    int cj = tid & 63, s = tid >> 6;
    int j = blockIdx.x * 64 + cj;
    bool jv = j < N;

    float acc[8];
#pragma unroll
    for (int b = 0; b < 8; b++) acc[b] = 0.f;

    for (int k0 = 0; k0 < K; k0 += 512) {
        for (int i = tid; i < 8 * 512; i += 256)
            xs[i] = x[(long)(i >> 9) * K + k0 + (i & 511)];
        __syncthreads();
        if (jv) {
            int kb = s * 128;
            for (int kk = kb; kk < kb + 128; kk++) {
                float wv = w[(long)(k0 + kk) * N + j];
#pragma unroll
                for (int b = 0; b < 8; b++) acc[b] += xs[b * 512 + kk] * wv;
            }
        }
        __syncthreads();
    }
#pragma unroll
    for (int b = 0; b < 8; b++) red_[s][cj][b] = acc[b];
    __syncthreads();
    if (s == 0 && jv) {
#pragma unroll
        for (int b = 0; b < 8; b++) {
            float v = red_[0][cj][b] + red_[1][cj][b] + red_[2][cj][b] + red_[3][cj][b]
                    + bias[j];
            y[(long)b * N + j] = do_relu ? fmaxf(v, 0.f) : v;
        }
    }
}

// ---------------------------------------------------------------------------
extern "C" void kernel_launch(void* const* d_in, const int* in_sizes, int n_in,
                              void* d_out, int out_size) {
    const float* feats    = (const float*)d_in[0];
    const float* w[6]     = {(const float*)d_in[1], (const float*)d_in[2],
                             (const float*)d_in[3], (const float*)d_in[4],
                             (const float*)d_in[5], (const float*)d_in[6]};
    const float* bn_gamma = (const float*)d_in[7];
    const float* bn_beta  = (const float*)d_in[8];
    const float* fc1_w = (const float*)d_in[9];
    const float* fc1_b = (const float*)d_in[10];
    const float* fc2_w = (const float*)d_in[11];
    const float* fc2_b = (const float*)d_in[12];
    const float* fc3_w = (const float*)d_in[13];
    const float* fc3_b = (const float*)d_in[14];
    const int* map1_in  = (const int*)d_in[15];
    const int* map1_out = (const int*)d_in[16];
    const int* map2_in  = (const int*)d_in[17];
    const int* map2_out = (const int*)d_in[18];
    const int* pool1_idx = (const int*)d_in[19];
    const int* pool2_idx = (const int*)d_in[20];
    const int* batch_idx = (const int*)d_in[21];

    int n1 = in_sizes[19];
    int n2 = in_sizes[20];
    int n3 = in_sizes[21];
    int P1 = in_sizes[15] / 27;
    int P2 = in_sizes[17] / 27;

    float *acc, *glob, *fcb1, *fcb2;
    __half *hA, *hB, *wh;
    int *cnt1, *cnt2;
    cudaGetSymbolAddress((void**)&acc, g_acc);
    cudaGetSymbolAddress((void**)&hA, g_hA);
    cudaGetSymbolAddress((void**)&hB, g_hB);
    cudaGetSymbolAddress((void**)&wh, g_wh);
    cudaGetSymbolAddress((void**)&glob, g_glob);
    cudaGetSymbolAddress((void**)&fcb1, g_fcb1);
    cudaGetSymbolAddress((void**)&fcb2, g_fcb2);
    cudaGetSymbolAddress((void**)&cnt1, g_cnt1);
    cudaGetSymbolAddress((void**)&cnt2, g_cnt2);

    static int smem_set = 0;
    if (!smem_set) {
        cudaFuncSetAttribute(k_conv_off,
                             cudaFuncAttributeMaxDynamicSharedMemorySize, SMEM_BYTES);
        cudaFuncSetAttribute(k_conv_center,
                             cudaFuncAttributeMaxDynamicSharedMemorySize, SMEM_BYTES);
        smem_set = 1;
    }

    long wofs[6];
    wofs[0] = 0;
    for (int l = 1; l < 6; l++)
        wofs[l] = wofs[l - 1] + (long)27 * 512 * (l == 1 ? 256 : 512);

    dim3 wtblk(32, 8);

    auto conv27 = [&](const __half* xin, const __half* Wc, int Kdim,
                      const int* m_in, const int* m_out, int* cnts, int P) {
        dim3 grid((P + BM - 1) / BM, 512 / BN, 27);
        k_conv_off<<<grid, 512, SMEM_BYTES>>>(xin, Wc, m_in, m_out, cnts, P, Kdim,
                                              0, acc);
    };
    auto convC = [&](const __half* xin, const __half* Wc, int Kdim,
                     const int* m_in, const int* m_out, int* cnts, int P, int n) {
        dim3 gc((n + BM - 1) / BM, 512 / BN);
        k_conv_center<<<gc, 512, SMEM_BYTES>>>(xin, Wc + (long)13 * 512 * Kdim,
                                               n, Kdim, acc);
        dim3 go((P + BM - 1) / BM, 512 / BN, 26);
        k_conv_off<<<go, 512, SMEM_BYTES>>>(xin, Wc, m_in, m_out, cnts, P, Kdim,
                                            1, acc);
    };
    auto bn = [&](int n, int layer, __half* hout) {
        k_bn_stats<<<(n + 127) / 128, 256>>>(acc, n);
        k_bn_coef<<<1, 512>>>(bn_gamma + layer * 512, bn_beta + layer * 512,
                              1.0f / (float)n);
        int total8 = n * 64;
        int blocks = min((total8 + 255) / 256, 8192);
        k_bn_apply_h<<<blocks, 256>>>(acc, hout, total8);
    };

    // ---- launch order: my 4th kernel launch = conv1 (ncu target) ----
    k_wt<<<dim3(16, 256 / 32, 27), wtblk>>>(w[0], wh + wofs[0], 256);    // 0
    k_f2h<<<4096, 256>>>(feats, hA, n1 * 256);                           // 1
    k_count<<<27, 256>>>(map1_out, P1, n1, cnt1);                        // 2
    cudaMemsetAsync(acc, 0, (long)n1 * 512 * 4);                         // (uncounted)
    conv27(hA, wh + wofs[0], 256, map1_in, map1_out, cnt1, P1);          // 3 <- ncu
    k_count<<<27, 256>>>(map2_out, P2, n2, cnt2);
    for (int l = 1; l < 6; l++)
        k_wt<<<dim3(16, 512 / 32, 27), wtblk>>>(w[l], wh + wofs[l], 512);
    bn(n1, 0, hB);

    convC(hB, wh + wofs[1], 512, map1_in, map1_out, cnt1, P1, n1); bn(n1, 1, hA);
    convC(hA, wh + wofs[2], 512, map1_in, map1_out, cnt1, P1, n1); bn(n1, 2, hB);

    // ---- pool1 ----
    cudaMemsetAsync(acc, 0, (long)n2 * 512 * 4);
    k_pool_max_h<<<4096, 256>>>(hB, pool1_idx, acc, n1);
    k_f2h<<<4096, 256>>>(acc, hA, n2 * 512);

    // ---- level 2 ----
    convC(hA, wh + wofs[3], 512, map2_in, map2_out, cnt2, P2, n2); bn(n2, 3, hB);
    convC(hB, wh + wofs[4], 512, map2_in, map2_out, cnt2, P2, n2); bn(n2, 4, hA);
    convC(hA, wh + wofs[5], 512, map2_in, map2_out, cnt2, P2, n2); bn(n2, 5, hB);

    // ---- pool2 + global max ----
    cudaMemsetAsync(acc, 0, (long)n3 * 512 * 4);
    k_pool_max_h<<<2048, 256>>>(hB, pool2_idx, acc, n2);
    cudaMemsetAsync(glob, 0, 8 * 512 * 4);
    k_pool_max_f<<<512, 256>>>(acc, batch_idx, glob, n3);

    // ---- FC head ----
    k_fc<<<64, 256>>>(glob, fc1_w, fc1_b, fcb1, 512, 4096, 1);
    k_fc<<<64, 256>>>(fcb1, fc2_w, fc2_b, fcb2, 4096, 4096, 1);
    k_fc<<<1, 256>>>(fcb2, fc3_w, fc3_b, (float*)d_out, 4096, 40, 0);
}

// round 15
// speedup vs baseline: 1.4954x; 1.4954x over previous
#include <cuda_runtime.h>
#include <cuda_fp16.h>
#include <cstdint>

// ---------------------------------------------------------------------------
// Sparse 3D CNN pipeline. Round 15: round-13 champion conv (fp16 HMMA, BK=32,
// 4-stage cp.async, quad-shuffle red.v4 scatter, center-split) + tail trims:
// conv1 center-split (no memset), fused 5-layer weight convert, BN coef
// computed by last stats block (launch removed).
// ---------------------------------------------------------------------------

__device__ float  g_acc[32768 * 512];
__device__ __half g_hA[32768 * 512];
__device__ __half g_hB[32768 * 512];
__device__ __half g_wh[38928384];               // fp16 weights [27][512][ci]
__device__ float  g_sum[512];
__device__ float  g_sumsq[512];
__device__ float  g_coefA[512];
__device__ float  g_coefB[512];
__device__ int    g_cnt1[27];
__device__ int    g_cnt2[27];
__device__ int    g_done;
__device__ float  g_glob[8 * 512];
__device__ float  g_fcb1[8 * 4096];
__device__ float  g_fcb2[8 * 4096];

#define BM 128
#define BN 128
#define BK 32
#define STAGES 4
#define ALDH 40
#define BLDH 40

#define AH_OFF 0
#define A_ST_H (BM * ALDH)
#define BH_OFF (STAGES * A_ST_H)
#define B_ST_H (BN * BLDH)
#define IDX_OFF (BH_OFF + STAGES * B_ST_H)
#define SMEM_BYTES (IDX_OFF * 2 + 2 * BM * 4)

static __device__ __forceinline__ uint32_t smem_u32(const void* p) {
    uint32_t a;
    asm("{ .reg .u64 t; cvta.to.shared.u64 t, %1; cvt.u32.u64 %0, t; }"
        : "=r"(a) : "l"(p));
    return a;
}
static __device__ __forceinline__ void cp16(uint32_t dst, const void* src, bool v) {
    asm volatile("cp.async.cg.shared.global [%0], [%1], 16, %2;"
                 :: "r"(dst), "l"(src), "r"(v ? 16 : 0));
}
static __device__ __forceinline__ void cp16ca(uint32_t dst, const void* src) {
    asm volatile("cp.async.ca.shared.global [%0], [%1], 16;"
                 :: "r"(dst), "l"(src));
}
#define CP_COMMIT() asm volatile("cp.async.commit_group;" ::: "memory")
#define CP_WAIT2()  asm volatile("cp.async.wait_group 2;" ::: "memory")

static __device__ __forceinline__ void ldsm4(uint32_t& r0, uint32_t& r1,
                                             uint32_t& r2, uint32_t& r3,
                                             uint32_t addr) {
    asm volatile("ldmatrix.sync.aligned.m8n8.x4.shared.b16 {%0,%1,%2,%3}, [%4];"
                 : "=r"(r0), "=r"(r1), "=r"(r2), "=r"(r3) : "r"(addr));
}
static __device__ __forceinline__ void red4(float* p, float v0, float v1,
                                            float v2, float v3) {
    asm volatile("red.global.add.v4.f32 [%0], {%1,%2,%3,%4};"
                 :: "l"(p), "f"(v0), "f"(v1), "f"(v2), "f"(v3) : "memory");
}

__global__ void k_count(const int* __restrict__ out_idx, int P, int sentinel,
                        int* __restrict__ counts) {
    int k = blockIdx.x;
    const int* o = out_idx + (long)k * P;
    int c = 0;
    for (int p = threadIdx.x; p < P; p += blockDim.x) c += (o[p] != sentinel);
    __shared__ int sm[256];
    sm[threadIdx.x] = c;
    __syncthreads();
    for (int s = 128; s > 0; s >>= 1) {
        if (threadIdx.x < s) sm[threadIdx.x] += sm[threadIdx.x + s];
        __syncthreads();
    }
    if (threadIdx.x == 0) counts[k] = sm[0];
}

// Single-layer convert: W[27][ci][512] f32 -> Wh[27][512][ci] half.
__global__ void k_wt(const float* __restrict__ W, __half* __restrict__ out, int ci) {
    __shared__ float t[32][33];
    int k = blockIdx.z;
    int i0 = blockIdx.y * 32, o0 = blockIdx.x * 32;
    int tx = threadIdx.x, ty = threadIdx.y;
#pragma unroll
    for (int r = 0; r < 32; r += 8)
        t[ty + r][tx] = W[((long)k * ci + i0 + ty + r) * 512 + o0 + tx];
    __syncthreads();
#pragma unroll
    for (int r = 0; r < 32; r += 8)
        out[((long)k * 512 + o0 + ty + r) * ci + i0 + tx] = __float2half(t[tx][ty + r]);
}

// Fused convert for 5 identical 512-ci layers; z = layer*27 + k.
__global__ void k_wt5(const float* w1, const float* w2, const float* w3,
                      const float* w4, const float* w5,
                      __half* __restrict__ out0, long stride) {
    __shared__ float t[32][33];
    int layer = blockIdx.z / 27;
    int k = blockIdx.z % 27;
    const float* W = (layer == 0) ? w1 : (layer == 1) ? w2 : (layer == 2) ? w3
                   : (layer == 3) ? w4 : w5;
    __half* out = out0 + (long)layer * stride;
    int i0 = blockIdx.y * 32, o0 = blockIdx.x * 32;
    int tx = threadIdx.x, ty = threadIdx.y;
#pragma unroll
    for (int r = 0; r < 32; r += 8)
        t[ty + r][tx] = W[((long)k * 512 + i0 + ty + r) * 512 + o0 + tx];
    __syncthreads();
#pragma unroll
    for (int r = 0; r < 32; r += 8)
        out[((long)k * 512 + o0 + ty + r) * 512 + i0 + tx] = __float2half(t[tx][ty + r]);
}

__global__ void k_f2h(const float* __restrict__ x, __half* __restrict__ y, int n) {
    int i = blockIdx.x * blockDim.x + threadIdx.x;
    int stride = gridDim.x * blockDim.x;
    for (; i < n; i += stride) y[i] = __float2half(x[i]);
}

// ---------------------------------------------------------------------------
// Gather conv: offsets via blockIdx.z (skip13 removes center), v4 red scatter.
// ---------------------------------------------------------------------------
__global__ __launch_bounds__(256, 2)
void k_conv_off(const __half* __restrict__ x, const __half* __restrict__ Wh,
                const int* __restrict__ in_idx, const int* __restrict__ out_idx,
                const int* __restrict__ counts, int P, int K, int skip13,
                float* __restrict__ out) {
    int koff = blockIdx.z;
    if (skip13 && koff >= 13) koff++;
    int count = counts[koff];
    int row0 = blockIdx.x * BM;
    if (row0 >= count) return;
    int col0 = blockIdx.y * BN;
    const __half* Wk = Wh + (long)koff * 512 * K;

    extern __shared__ __half smh[];
    int* rs = (int*)(smh + IDX_OFF);
    int* os = rs + BM;

    int tid = threadIdx.x;
    if (tid < BM) {
        int p = row0 + tid;
        bool v = p < count;
        rs[tid] = v ? in_idx[(long)koff * P + p] : -1;
        os[tid] = v ? out_idx[(long)koff * P + p] : -1;
    }
    __syncthreads();

    int lrow = tid >> 1;
    int lseg = (tid & 1) * 16;
    int ar = rs[lrow];
    const __half* xrow = (ar >= 0) ? &x[(long)ar * K] : nullptr;
    const __half* wcol = &Wk[(long)(col0 + lrow) * K];

    uint32_t As_u = smem_u32(smh + AH_OFF);
    uint32_t Bs_u = smem_u32(smh + BH_OFF);

    auto issue_stage = [&](int stage, int k0) {
        uint32_t Ab = As_u + stage * A_ST_H * 2;
        uint32_t Bb = Bs_u + stage * B_ST_H * 2;
        const __half* asrc = xrow ? (xrow + k0 + lseg) : x;
        cp16(Ab + (lrow * ALDH + lseg) * 2,     asrc,     xrow != nullptr);
        cp16(Ab + (lrow * ALDH + lseg + 8) * 2, asrc + 8, xrow != nullptr);
        const __half* bsrc = wcol + k0 + lseg;
        cp16ca(Bb + (lrow * BLDH + lseg) * 2,     bsrc);
        cp16ca(Bb + (lrow * BLDH + lseg + 8) * 2, bsrc + 8);
        CP_COMMIT();
    };

    int warp = tid >> 5, lane = tid & 31;
    int wm = warp & 1, wn = warp >> 1;
    int lg = lane >> 3, lr8 = lane & 7;

    float acc[4][4][4];
#pragma unroll
    for (int mt = 0; mt < 4; mt++)
#pragma unroll
        for (int nt = 0; nt < 4; nt++)
#pragma unroll
            for (int i = 0; i < 4; i++) acc[mt][nt][i] = 0.0f;

    int nIter = K / BK;
    issue_stage(0, 0);
    if (nIter > 1) issue_stage(1, BK);
    if (nIter > 2) issue_stage(2, 2 * BK);

    for (int it = 0; it < nIter; it++) {
        CP_WAIT2();
        __syncthreads();
        if (it + 3 < nIter) issue_stage((it + 3) % STAGES, (it + 3) * BK);

        uint32_t Af = As_u + (it % STAGES) * A_ST_H * 2;
        uint32_t Bf = Bs_u + (it % STAGES) * B_ST_H * 2;

#pragma unroll
        for (int h = 0; h < 2; h++) {
            int kb = h * 16;
            uint32_t a[4][4];
#pragma unroll
            for (int mt = 0; mt < 4; mt++) {
                int rowa = wm * 64 + mt * 16 + lr8 + (lg & 1) * 8;
                int ka = kb + (lg >> 1) * 8;
                ldsm4(a[mt][0], a[mt][1], a[mt][2], a[mt][3],
                      Af + (rowa * ALDH + ka) * 2);
            }
            uint32_t b[4][2];
#pragma unroll
            for (int np = 0; np < 2; np++) {
                int rowb = wn * 32 + np * 16 + lr8 + (lg & 1) * 8;
                int kber = kb + (lg >> 1) * 8;
                uint32_t r0, r1, r2, r3;
                ldsm4(r0, r1, r2, r3, Bf + (rowb * BLDH + kber) * 2);
                b[np * 2 + 0][0] = r0; b[np * 2 + 0][1] = r2;
                b[np * 2 + 1][0] = r1; b[np * 2 + 1][1] = r3;
            }
#pragma unroll
            for (int mt = 0; mt < 4; mt++)
#pragma unroll
                for (int nt = 0; nt < 4; nt++) {
                    asm volatile(
                        "mma.sync.aligned.m16n8k16.row.col.f32.f16.f16.f32 "
                        "{%0,%1,%2,%3}, {%4,%5,%6,%7}, {%8,%9}, {%0,%1,%2,%3};"
                        : "+f"(acc[mt][nt][0]), "+f"(acc[mt][nt][1]),
                          "+f"(acc[mt][nt][2]), "+f"(acc[mt][nt][3])
                        : "r"(a[mt][0]), "r"(a[mt][1]), "r"(a[mt][2]), "r"(a[mt][3]),
                          "r"(b[nt][0]), "r"(b[nt][1]));
                }
        }
    }

    int lr = lane >> 2, lq = lane & 3;
    int odd = lane & 1;
#pragma unroll
    for (int mt = 0; mt < 4; mt++) {
        int rbase = wm * 64 + mt * 16 + lr;
        int o_lo = os[rbase];
        int o_hi = os[rbase + 8];
        int o = odd ? o_hi : o_lo;
#pragma unroll
        for (int nt = 0; nt < 4; nt++) {
            float e0 = __shfl_xor_sync(0xffffffffu, acc[mt][nt][0], 1);
            float e1 = __shfl_xor_sync(0xffffffffu, acc[mt][nt][1], 1);
            float e2 = __shfl_xor_sync(0xffffffffu, acc[mt][nt][2], 1);
            float e3 = __shfl_xor_sync(0xffffffffu, acc[mt][nt][3], 1);
            float v0, v1, v2, v3;
            if (!odd) { v0 = acc[mt][nt][0]; v1 = acc[mt][nt][1]; v2 = e0; v3 = e1; }
            else      { v0 = e2; v1 = e3; v2 = acc[mt][nt][2]; v3 = acc[mt][nt][3]; }
            int cb = col0 + wn * 32 + nt * 8 + (lq & 2) * 2;
            if (o >= 0) red4(&out[(long)o * 512 + cb], v0, v1, v2, v3);
        }
    }
}

// ---------------------------------------------------------------------------
// Center offset: identity map -> dense GEMM, coalesced v4 stores, initializes.
// ---------------------------------------------------------------------------
__global__ __launch_bounds__(256, 2)
void k_conv_center(const __half* __restrict__ x, const __half* __restrict__ W13,
                   int n, int K, float* __restrict__ out) {
    int row0 = blockIdx.x * BM;
    int col0 = blockIdx.y * BN;

    extern __shared__ __half smh[];
    int tid = threadIdx.x;
    int lrow = tid >> 1;
    int lseg = (tid & 1) * 16;
    int grow = row0 + lrow;
    const __half* xrow = (grow < n) ? &x[(long)grow * K] : nullptr;
    const __half* wcol = &W13[(long)(col0 + lrow) * K];

    uint32_t As_u = smem_u32(smh + AH_OFF);
    uint32_t Bs_u = smem_u32(smh + BH_OFF);

    auto issue_stage = [&](int stage, int k0) {
        uint32_t Ab = As_u + stage * A_ST_H * 2;
        uint32_t Bb = Bs_u + stage * B_ST_H * 2;
        const __half* asrc = xrow ? (xrow + k0 + lseg) : x;
        cp16(Ab + (lrow * ALDH + lseg) * 2,     asrc,     xrow != nullptr);
        cp16(Ab + (lrow * ALDH + lseg + 8) * 2, asrc + 8, xrow != nullptr);
        const __half* bsrc = wcol + k0 + lseg;
        cp16ca(Bb + (lrow * BLDH + lseg) * 2,     bsrc);
        cp16ca(Bb + (lrow * BLDH + lseg + 8) * 2, bsrc + 8);
        CP_COMMIT();
    };

    int warp = tid >> 5, lane = tid & 31;
    int wm = warp & 1, wn = warp >> 1;
    int lg = lane >> 3, lr8 = lane & 7;

    float acc[4][4][4];
#pragma unroll
    for (int mt = 0; mt < 4; mt++)
#pragma unroll
        for (int nt = 0; nt < 4; nt++)
#pragma unroll
            for (int i = 0; i < 4; i++) acc[mt][nt][i] = 0.0f;

    int nIter = K / BK;
    issue_stage(0, 0);
    if (nIter > 1) issue_stage(1, BK);
    if (nIter > 2) issue_stage(2, 2 * BK);

    for (int it = 0; it < nIter; it++) {
        CP_WAIT2();
        __syncthreads();
        if (it + 3 < nIter) issue_stage((it + 3) % STAGES, (it + 3) * BK);

        uint32_t Af = As_u + (it % STAGES) * A_ST_H * 2;
        uint32_t Bf = Bs_u + (it % STAGES) * B_ST_H * 2;

#pragma unroll
        for (int h = 0; h < 2; h++) {
            int kb = h * 16;
            uint32_t a[4][4];
#pragma unroll
            for (int mt = 0; mt < 4; mt++) {
                int rowa = wm * 64 + mt * 16 + lr8 + (lg & 1) * 8;
                int ka = kb + (lg >> 1) * 8;
                ldsm4(a[mt][0], a[mt][1], a[mt][2], a[mt][3],
                      Af + (rowa * ALDH + ka) * 2);
            }
            uint32_t b[4][2];
#pragma unroll
            for (int np = 0; np < 2; np++) {
                int rowb = wn * 32 + np * 16 + lr8 + (lg & 1) * 8;
                int kber = kb + (lg >> 1) * 8;
                uint32_t r0, r1, r2, r3;
                ldsm4(r0, r1, r2, r3, Bf + (rowb * BLDH + kber) * 2);
                b[np * 2 + 0][0] = r0; b[np * 2 + 0][1] = r2;
                b[np * 2 + 1][0] = r1; b[np * 2 + 1][1] = r3;
            }
#pragma unroll
            for (int mt = 0; mt < 4; mt++)
#pragma unroll
                for (int nt = 0; nt < 4; nt++) {
                    asm volatile(
                        "mma.sync.aligned.m16n8k16.row.col.f32.f16.f16.f32 "
                        "{%0,%1,%2,%3}, {%4,%5,%6,%7}, {%8,%9}, {%0,%1,%2,%3};"
                        : "+f"(acc[mt][nt][0]), "+f"(acc[mt][nt][1]),
                          "+f"(acc[mt][nt][2]), "+f"(acc[mt][nt][3])
                        : "r"(a[mt][0]), "r"(a[mt][1]), "r"(a[mt][2]), "r"(a[mt][3]),
                          "r"(b[nt][0]), "r"(b[nt][1]));
                }
        }
    }

    int lr = lane >> 2, lq = lane & 3;
    int odd = lane & 1;
#pragma unroll
    for (int mt = 0; mt < 4; mt++) {
        int r_lo = row0 + wm * 64 + mt * 16 + lr;
        int r = odd ? (r_lo + 8) : r_lo;
#pragma unroll
        for (int nt = 0; nt < 4; nt++) {
            float e0 = __shfl_xor_sync(0xffffffffu, acc[mt][nt][0], 1);
            float e1 = __shfl_xor_sync(0xffffffffu, acc[mt][nt][1], 1);
            float e2 = __shfl_xor_sync(0xffffffffu, acc[mt][nt][2], 1);
            float e3 = __shfl_xor_sync(0xffffffffu, acc[mt][nt][3], 1);
            float4 v;
            if (!odd) { v.x = acc[mt][nt][0]; v.y = acc[mt][nt][1]; v.z = e0; v.w = e1; }
            else      { v.x = e2; v.y = e3; v.z = acc[mt][nt][2]; v.w = acc[mt][nt][3]; }
            int cb = col0 + wn * 32 + nt * 8 + (lq & 2) * 2;
            if (r < n) *(float4*)&out[(long)r * 512 + cb] = v;
        }
    }
}

// ---------------------------------------------------------------------------
// BN stats + (last block) coef. g_sum/g_sumsq/g_done self-resetting.
// ---------------------------------------------------------------------------
__global__ void k_bn_stats(const float* __restrict__ x, int n,
                           const float* __restrict__ gamma,
                           const float* __restrict__ beta, float inv_n) {
    int c = threadIdx.x;
    int r0 = blockIdx.x * 128;
    int rend = min(r0 + 128, n);
    float s0 = 0.f, s20 = 0.f, s1 = 0.f, s21 = 0.f;
    for (int r = r0; r < rend; r++) {
        float v0 = x[(long)r * 512 + c];
        float v1 = x[(long)r * 512 + c + 256];
        s0 += v0; s20 += v0 * v0;
        s1 += v1; s21 += v1 * v1;
    }
    atomicAdd(&g_sum[c], s0);
    atomicAdd(&g_sumsq[c], s20);
    atomicAdd(&g_sum[c + 256], s1);
    atomicAdd(&g_sumsq[c + 256], s21);

    __threadfence();
    __shared__ int is_last;
    if (threadIdx.x == 0)
        is_last = (atomicAdd(&g_done, 1) == (int)gridDim.x - 1);
    __syncthreads();
    if (is_last) {
        __threadfence();
#pragma unroll
        for (int half = 0; half < 2; half++) {
            int ch = c + half * 256;
            float mu = g_sum[ch] * inv_n;
            float var = g_sumsq[ch] * inv_n - mu * mu;
            float a = gamma[ch] * rsqrtf(var + 1e-5f);
            g_coefA[ch] = a;
            g_coefB[ch] = beta[ch] - mu * a;
            g_sum[ch] = 0.0f;
            g_sumsq[ch] = 0.0f;
        }
        if (threadIdx.x == 0) g_done = 0;
    }
}

__global__ void k_bn_apply_h(const float* __restrict__ x, __half* __restrict__ y,
                             int total8) {
    int i = blockIdx.x * blockDim.x + threadIdx.x;
    int stride = gridDim.x * blockDim.x;
    for (; i < total8; i += stride) {
        float4 v0 = ((const float4*)x)[i * 2];
        float4 v1 = ((const float4*)x)[i * 2 + 1];
        int c = (i * 8) & 511;
        float4 a0 = *(const float4*)&g_coefA[c];
        float4 a1 = *(const float4*)&g_coefA[c + 4];
        float4 b0 = *(const float4*)&g_coefB[c];
        float4 b1 = *(const float4*)&g_coefB[c + 4];
        __half2 h[4];
        h[0] = __floats2half2_rn(fmaxf(v0.x * a0.x + b0.x, 0.f), fmaxf(v0.y * a0.y + b0.y, 0.f));
        h[1] = __floats2half2_rn(fmaxf(v0.z * a0.z + b0.z, 0.f), fmaxf(v0.w * a0.w + b0.w, 0.f));
        h[2] = __floats2half2_rn(fmaxf(v1.x * a1.x + b1.x, 0.f), fmaxf(v1.y * a1.y + b1.y, 0.f));
        h[3] = __floats2half2_rn(fmaxf(v1.z * a1.z + b1.z, 0.f), fmaxf(v1.w * a1.w + b1.w, 0.f));
        ((uint4*)y)[i] = *(const uint4*)h;
    }
}

// ---------------------------------------------------------------------------
__global__ void k_pool_max_h(const __half* __restrict__ x, const int* __restrict__ idx,
                             float* __restrict__ out, int n_in) {
    long total = (long)n_in * 512;
    long i = (long)blockIdx.x * blockDim.x + threadIdx.x;
    long stride = (long)gridDim.x * blockDim.x;
    for (; i < total; i += stride) {
        int r = (int)(i >> 9);
        int c = (int)(i & 511);
        float v = __half2float(x[i]);
        atomicMax((int*)&out[(long)idx[r] * 512 + c], __float_as_int(v));
    }
}

__global__ void k_pool_max_f(const float* __restrict__ x, const int* __restrict__ idx,
                             float* __restrict__ out, int n_in) {
    long total = (long)n_in * 512;
    long i = (long)blockIdx.x * blockDim.x + threadIdx.x;
    long stride = (long)gridDim.x * blockDim.x;
    for (; i < total; i += stride) {
        int r = (int)(i >> 9);
        int c = (int)(i & 511);
        float v = x[i];
        atomicMax((int*)&out[(long)idx[r] * 512 + c], __float_as_int(v));
    }
}

// ---------------------------------------------------------------------------
__global__ __launch_bounds__(256)
void k_fc(const float* __restrict__ x, const float* __restrict__ w,
          const float* __restrict__ bias, float* __restrict__ y,
          int K, int N, int do_relu) {
    __shared__ float xs[8 * 512];
    __shared__ float red_[4][64][8];
    int tid = threadIdx.x;
    int cj = tid & 63, s = tid >> 6;
    int j = blockIdx.x * 64 + cj;
    bool jv = j < N;

    float acc[8];
#pragma unroll
    for (int b = 0; b < 8; b++) acc[b] = 0.f;

    for (int k0 = 0; k0 < K; k0 += 512) {
        for (int i = tid; i < 8 * 512; i += 256)
            xs[i] = x[(long)(i >> 9) * K + k0 + (i & 511)];
        __syncthreads();
        if (jv) {
            int kb = s * 128;
            for (int kk = kb; kk < kb + 128; kk++) {
                float wv = w[(long)(k0 + kk) * N + j];
#pragma unroll
                for (int b = 0; b < 8; b++) acc[b] += xs[b * 512 + kk] * wv;
            }
        }
        __syncthreads();
    }
#pragma unroll
    for (int b = 0; b < 8; b++) red_[s][cj][b] = acc[b];
    __syncthreads();
    if (s == 0 && jv) {
#pragma unroll
        for (int b = 0; b < 8; b++) {
            float v = red_[0][cj][b] + red_[1][cj][b] + red_[2][cj][b] + red_[3][cj][b]
                    + bias[j];
            y[(long)b * N + j] = do_relu ? fmaxf(v, 0.f) : v;
        }
    }
}

// ---------------------------------------------------------------------------
extern "C" void kernel_launch(void* const* d_in, const int* in_sizes, int n_in,
                              void* d_out, int out_size) {
    const float* feats    = (const float*)d_in[0];
    const float* w[6]     = {(const float*)d_in[1], (const float*)d_in[2],
                             (const float*)d_in[3], (const float*)d_in[4],
                             (const float*)d_in[5], (const float*)d_in[6]};
    const float* bn_gamma = (const float*)d_in[7];
    const float* bn_beta  = (const float*)d_in[8];
    const float* fc1_w = (const float*)d_in[9];
    const float* fc1_b = (const float*)d_in[10];
    const float* fc2_w = (const float*)d_in[11];
    const float* fc2_b = (const float*)d_in[12];
    const float* fc3_w = (const float*)d_in[13];
    const float* fc3_b = (const float*)d_in[14];
    const int* map1_in  = (const int*)d_in[15];
    const int* map1_out = (const int*)d_in[16];
    const int* map2_in  = (const int*)d_in[17];
    const int* map2_out = (const int*)d_in[18];
    const int* pool1_idx = (const int*)d_in[19];
    const int* pool2_idx = (const int*)d_in[20];
    const int* batch_idx = (const int*)d_in[21];

    int n1 = in_sizes[19];
    int n2 = in_sizes[20];
    int n3 = in_sizes[21];
    int P1 = in_sizes[15] / 27;
    int P2 = in_sizes[17] / 27;

    float *acc, *glob, *fcb1, *fcb2;
    __half *hA, *hB, *wh;
    int *cnt1, *cnt2;
    cudaGetSymbolAddress((void**)&acc, g_acc);
    cudaGetSymbolAddress((void**)&hA, g_hA);
    cudaGetSymbolAddress((void**)&hB, g_hB);
    cudaGetSymbolAddress((void**)&wh, g_wh);
    cudaGetSymbolAddress((void**)&glob, g_glob);
    cudaGetSymbolAddress((void**)&fcb1, g_fcb1);
    cudaGetSymbolAddress((void**)&fcb2, g_fcb2);
    cudaGetSymbolAddress((void**)&cnt1, g_cnt1);
    cudaGetSymbolAddress((void**)&cnt2, g_cnt2);

    static int smem_set = 0;
    if (!smem_set) {
        cudaFuncSetAttribute(k_conv_off,
                             cudaFuncAttributeMaxDynamicSharedMemorySize, SMEM_BYTES);
        cudaFuncSetAttribute(k_conv_center,
                             cudaFuncAttributeMaxDynamicSharedMemorySize, SMEM_BYTES);
        smem_set = 1;
    }

    long wofs[6];
    wofs[0] = 0;
    for (int l = 1; l < 6; l++)
        wofs[l] = wofs[l - 1] + (long)27 * 512 * (l == 1 ? 256 : 512);
    long wstride = (long)27 * 512 * 512;

    dim3 wtblk(32, 8);

    auto convC = [&](const __half* xin, const __half* Wc, int Kdim,
                     const int* m_in, const int* m_out, int* cnts, int P, int n) {
        dim3 gc((n + BM - 1) / BM, 512 / BN);
        k_conv_center<<<gc, 256, SMEM_BYTES>>>(xin, Wc + (long)13 * 512 * Kdim,
                                               n, Kdim, acc);
        dim3 go((P + BM - 1) / BM, 512 / BN, 26);
        k_conv_off<<<go, 256, SMEM_BYTES>>>(xin, Wc, m_in, m_out, cnts, P, Kdim,
                                            1, acc);
    };
    auto bn = [&](int n, int layer, __half* hout) {
        k_bn_stats<<<(n + 127) / 128, 256>>>(acc, n, bn_gamma + layer * 512,
                                             bn_beta + layer * 512,
                                             1.0f / (float)n);
        int total8 = n * 64;
        int blocks = min((total8 + 255) / 256, 8192);
        k_bn_apply_h<<<blocks, 256>>>(acc, hout, total8);
    };

    // ---- prologue ----
    k_wt<<<dim3(16, 256 / 32, 27), wtblk>>>(w[0], wh + wofs[0], 256);
    k_f2h<<<4096, 256>>>(feats, hA, n1 * 256);
    k_count<<<27, 256>>>(map1_out, P1, n1, cnt1);
    k_count<<<27, 256>>>(map2_out, P2, n2, cnt2);

    // ---- level 1 ----
    convC(hA, wh + wofs[0], 256, map1_in, map1_out, cnt1, P1, n1);
    // convert remaining 5 weight layers in one launch (overlaps conv1)
    k_wt5<<<dim3(16, 16, 135), wtblk>>>(w[1], w[2], w[3], w[4], w[5],
                                        wh + wofs[1], wstride);
    bn(n1, 0, hB);

    convC(hB, wh + wofs[1], 512, map1_in, map1_out, cnt1, P1, n1); bn(n1, 1, hA);
    convC(hA, wh + wofs[2], 512, map1_in, map1_out, cnt1, P1, n1); bn(n1, 2, hB);

    // ---- pool1 ----
    cudaMemsetAsync(acc, 0, (long)n2 * 512 * 4);
    k_pool_max_h<<<4096, 256>>>(hB, pool1_idx, acc, n1);
    k_f2h<<<4096, 256>>>(acc, hA, n2 * 512);

    // ---- level 2 ----
    convC(hA, wh + wofs[3], 512, map2_in, map2_out, cnt2, P2, n2); bn(n2, 3, hB);
    convC(hB, wh + wofs[4], 512, map2_in, map2_out, cnt2, P2, n2); bn(n2, 4, hA);
    convC(hA, wh + wofs[5], 512, map2_in, map2_out, cnt2, P2, n2); bn(n2, 5, hB);

    // ---- pool2 + global max ----
    cudaMemsetAsync(acc, 0, (long)n3 * 512 * 4);
    k_pool_max_h<<<2048, 256>>>(hB, pool2_idx, acc, n2);
    cudaMemsetAsync(glob, 0, 8 * 512 * 4);
    k_pool_max_f<<<512, 256>>>(acc, batch_idx, glob, n3);

    // ---- FC head ----
    k_fc<<<64, 256>>>(glob, fc1_w, fc1_b, fcb1, 512, 4096, 1);
    k_fc<<<64, 256>>>(fcb1, fc2_w, fc2_b, fcb2, 4096, 4096, 1);
    k_fc<<<1, 256>>>(fcb2, fc3_w, fc3_b, (float*)d_out, 4096, 40, 0);
}

// round 16
// speedup vs baseline: 1.5620x; 1.0446x over previous
#include <cuda_runtime.h>
#include <cuda_fp16.h>
#include <cstdint>

// ---------------------------------------------------------------------------
// Sparse 3D CNN pipeline. Round 16: champion conv (fp16 HMMA, BK=32, 4-stage
// cp.async, quad-shuffle red.v4, center-split) + tail rewrites: parallel
// k_count, CSR pool1 (no atomics, writes half), fused pool2+global via
// composed index, widened FC head.
// ---------------------------------------------------------------------------

__device__ float  g_acc[32768 * 512];
__device__ __half g_hA[32768 * 512];
__device__ __half g_hB[32768 * 512];
__device__ __half g_wh[38928384];               // fp16 weights [27][512][ci]
__device__ float  g_sum[512];
__device__ float  g_sumsq[512];
__device__ float  g_coefA[512];
__device__ float  g_coefB[512];
__device__ int    g_cnt1[27];
__device__ int    g_cnt2[27];
__device__ int    g_done;
__device__ int    g_seg1[32770];                // pool1 CSR offsets (n2+1)
__device__ int    g_ptr1[32768];
__device__ int    g_inv1[32768];
__device__ float  g_glob[8 * 512];
__device__ float  g_fcb1[8 * 4096];
__device__ float  g_fcb2[8 * 4096];

#define BM 128
#define BN 128
#define BK 32
#define STAGES 4
#define ALDH 40
#define BLDH 40

#define AH_OFF 0
#define A_ST_H (BM * ALDH)
#define BH_OFF (STAGES * A_ST_H)
#define B_ST_H (BN * BLDH)
#define IDX_OFF (BH_OFF + STAGES * B_ST_H)
#define SMEM_BYTES (IDX_OFF * 2 + 2 * BM * 4)

static __device__ __forceinline__ uint32_t smem_u32(const void* p) {
    uint32_t a;
    asm("{ .reg .u64 t; cvta.to.shared.u64 t, %1; cvt.u32.u64 %0, t; }"
        : "=r"(a) : "l"(p));
    return a;
}
static __device__ __forceinline__ void cp16(uint32_t dst, const void* src, bool v) {
    asm volatile("cp.async.cg.shared.global [%0], [%1], 16, %2;"
                 :: "r"(dst), "l"(src), "r"(v ? 16 : 0));
}
static __device__ __forceinline__ void cp16ca(uint32_t dst, const void* src) {
    asm volatile("cp.async.ca.shared.global [%0], [%1], 16;"
                 :: "r"(dst), "l"(src));
}
#define CP_COMMIT() asm volatile("cp.async.commit_group;" ::: "memory")
#define CP_WAIT2()  asm volatile("cp.async.wait_group 2;" ::: "memory")

static __device__ __forceinline__ void ldsm4(uint32_t& r0, uint32_t& r1,
                                             uint32_t& r2, uint32_t& r3,
                                             uint32_t addr) {
    asm volatile("ldmatrix.sync.aligned.m8n8.x4.shared.b16 {%0,%1,%2,%3}, [%4];"
                 : "=r"(r0), "=r"(r1), "=r"(r2), "=r"(r3) : "r"(addr));
}
static __device__ __forceinline__ void red4(float* p, float v0, float v1,
                                            float v2, float v3) {
    asm volatile("red.global.add.v4.f32 [%0], {%1,%2,%3,%4};"
                 :: "l"(p), "f"(v0), "f"(v1), "f"(v2), "f"(v3) : "memory");
}

// ---- parallel map-pair counting: grid (27, 8), counts pre-zeroed ----
__global__ void k_count_par(const int* __restrict__ out_idx, int P, int sentinel,
                            int* __restrict__ counts) {
    int k = blockIdx.x;
    const int* o = out_idx + (long)k * P;
    int chunk = (P + gridDim.y - 1) / gridDim.y;
    int lo = blockIdx.y * chunk;
    int hi = min(lo + chunk, P);
    int c = 0;
    for (int p = lo + threadIdx.x; p < hi; p += blockDim.x) c += (o[p] != sentinel);
    __shared__ int sm[256];
    sm[threadIdx.x] = c;
    __syncthreads();
    for (int s = 128; s > 0; s >>= 1) {
        if (threadIdx.x < s) sm[threadIdx.x] += sm[threadIdx.x + s];
        __syncthreads();
    }
    if (threadIdx.x == 0) atomicAdd(&counts[k], sm[0]);
}

// ---- pool1 CSR build ----
__global__ void k_hist(const int* __restrict__ idx, int n, int* __restrict__ segp1) {
    int i = blockIdx.x * blockDim.x + threadIdx.x;
    int stride = gridDim.x * blockDim.x;
    for (; i < n; i += stride) atomicAdd(&segp1[idx[i] + 1], 1);
}

// single-block inclusive scan over m ints; also ptr[i] = a[i] for i < m-1
__global__ void k_scan(int* __restrict__ a, int m, int* __restrict__ ptr) {
    __shared__ int sm[1024];
    __shared__ int carry;
    if (threadIdx.x == 0) carry = 0;
    __syncthreads();
    for (int base = 0; base < m; base += 1024) {
        int i = base + threadIdx.x;
        int v = (i < m) ? a[i] : 0;
        sm[threadIdx.x] = v;
        __syncthreads();
        for (int off = 1; off < 1024; off <<= 1) {
            int t = (threadIdx.x >= off) ? sm[threadIdx.x - off] : 0;
            __syncthreads();
            sm[threadIdx.x] += t;
            __syncthreads();
        }
        int val = sm[threadIdx.x] + carry;
        if (i < m) {
            a[i] = val;
            if (i < m - 1) ptr[i] = val;
        }
        __syncthreads();
        if (threadIdx.x == 0) carry += sm[1023];
        __syncthreads();
    }
}

__global__ void k_scatter(const int* __restrict__ idx, int n,
                          int* __restrict__ ptr, int* __restrict__ inv) {
    int i = blockIdx.x * blockDim.x + threadIdx.x;
    int stride = gridDim.x * blockDim.x;
    for (; i < n; i += stride) {
        int s = atomicAdd(&ptr[idx[i]], 1);
        inv[s] = i;
    }
}

// per-segment gather max: half in -> half out, no atomics
__global__ void k_pool_csr(const __half* __restrict__ x, const int* __restrict__ seg,
                           const int* __restrict__ inv, __half* __restrict__ y) {
    int sid = blockIdx.x;
    int s0 = seg[sid], s1 = seg[sid + 1];
    for (int c = threadIdx.x; c < 512; c += blockDim.x) {
        float m = 0.f;
        for (int j = s0; j < s1; j++)
            m = fmaxf(m, __half2float(x[(long)inv[j] * 512 + c]));
        y[(long)sid * 512 + c] = __float2half(m);
    }
}

// fused pool2+global: segment max with composed index batch_idx[pool2_idx[r]]
__global__ void k_pool_compose(const __half* __restrict__ x,
                               const int* __restrict__ p2,
                               const int* __restrict__ bidx,
                               float* __restrict__ glob, int n2) {
    long total = (long)n2 * 512;
    long i = (long)blockIdx.x * blockDim.x + threadIdx.x;
    long stride = (long)gridDim.x * blockDim.x;
    for (; i < total; i += stride) {
        int r = (int)(i >> 9);
        int c = (int)(i & 511);
        int b = bidx[p2[r]];
        float v = __half2float(x[i]);
        atomicMax((int*)&glob[(long)b * 512 + c], __float_as_int(v));
    }
}

// Single-layer convert: W[27][ci][512] f32 -> Wh[27][512][ci] half.
__global__ void k_wt(const float* __restrict__ W, __half* __restrict__ out, int ci) {
    __shared__ float t[32][33];
    int k = blockIdx.z;
    int i0 = blockIdx.y * 32, o0 = blockIdx.x * 32;
    int tx = threadIdx.x, ty = threadIdx.y;
#pragma unroll
    for (int r = 0; r < 32; r += 8)
        t[ty + r][tx] = W[((long)k * ci + i0 + ty + r) * 512 + o0 + tx];
    __syncthreads();
#pragma unroll
    for (int r = 0; r < 32; r += 8)
        out[((long)k * 512 + o0 + ty + r) * ci + i0 + tx] = __float2half(t[tx][ty + r]);
}

// Fused convert for 5 identical 512-ci layers; z = layer*27 + k.
__global__ void k_wt5(const float* w1, const float* w2, const float* w3,
                      const float* w4, const float* w5,
                      __half* __restrict__ out0, long stride) {
    __shared__ float t[32][33];
    int layer = blockIdx.z / 27;
    int k = blockIdx.z % 27;
    const float* W = (layer == 0) ? w1 : (layer == 1) ? w2 : (layer == 2) ? w3
                   : (layer == 3) ? w4 : w5;
    __half* out = out0 + (long)layer * stride;
    int i0 = blockIdx.y * 32, o0 = blockIdx.x * 32;
    int tx = threadIdx.x, ty = threadIdx.y;
#pragma unroll
    for (int r = 0; r < 32; r += 8)
        t[ty + r][tx] = W[((long)k * 512 + i0 + ty + r) * 512 + o0 + tx];
    __syncthreads();
#pragma unroll
    for (int r = 0; r < 32; r += 8)
        out[((long)k * 512 + o0 + ty + r) * 512 + i0 + tx] = __float2half(t[tx][ty + r]);
}

__global__ void k_f2h(const float* __restrict__ x, __half* __restrict__ y, int n) {
    int i = blockIdx.x * blockDim.x + threadIdx.x;
    int stride = gridDim.x * blockDim.x;
    for (; i < n; i += stride) y[i] = __float2half(x[i]);
}

// ---------------------------------------------------------------------------
// Gather conv: offsets via blockIdx.z (skip13 removes center), v4 red scatter.
// ---------------------------------------------------------------------------
__global__ __launch_bounds__(256, 2)
void k_conv_off(const __half* __restrict__ x, const __half* __restrict__ Wh,
                const int* __restrict__ in_idx, const int* __restrict__ out_idx,
                const int* __restrict__ counts, int P, int K, int skip13,
                float* __restrict__ out) {
    int koff = blockIdx.z;
    if (skip13 && koff >= 13) koff++;
    int count = counts[koff];
    int row0 = blockIdx.x * BM;
    if (row0 >= count) return;
    int col0 = blockIdx.y * BN;
    const __half* Wk = Wh + (long)koff * 512 * K;

    extern __shared__ __half smh[];
    int* rs = (int*)(smh + IDX_OFF);
    int* os = rs + BM;

    int tid = threadIdx.x;
    if (tid < BM) {
        int p = row0 + tid;
        bool v = p < count;
        rs[tid] = v ? in_idx[(long)koff * P + p] : -1;
        os[tid] = v ? out_idx[(long)koff * P + p] : -1;
    }
    __syncthreads();

    int lrow = tid >> 1;
    int lseg = (tid & 1) * 16;
    int ar = rs[lrow];
    const __half* xrow = (ar >= 0) ? &x[(long)ar * K] : nullptr;
    const __half* wcol = &Wk[(long)(col0 + lrow) * K];

    uint32_t As_u = smem_u32(smh + AH_OFF);
    uint32_t Bs_u = smem_u32(smh + BH_OFF);

    auto issue_stage = [&](int stage, int k0) {
        uint32_t Ab = As_u + stage * A_ST_H * 2;
        uint32_t Bb = Bs_u + stage * B_ST_H * 2;
        const __half* asrc = xrow ? (xrow + k0 + lseg) : x;
        cp16(Ab + (lrow * ALDH + lseg) * 2,     asrc,     xrow != nullptr);
        cp16(Ab + (lrow * ALDH + lseg + 8) * 2, asrc + 8, xrow != nullptr);
        const __half* bsrc = wcol + k0 + lseg;
        cp16ca(Bb + (lrow * BLDH + lseg) * 2,     bsrc);
        cp16ca(Bb + (lrow * BLDH + lseg + 8) * 2, bsrc + 8);
        CP_COMMIT();
    };

    int warp = tid >> 5, lane = tid & 31;
    int wm = warp & 1, wn = warp >> 1;
    int lg = lane >> 3, lr8 = lane & 7;

    float acc[4][4][4];
#pragma unroll
    for (int mt = 0; mt < 4; mt++)
#pragma unroll
        for (int nt = 0; nt < 4; nt++)
#pragma unroll
            for (int i = 0; i < 4; i++) acc[mt][nt][i] = 0.0f;

    int nIter = K / BK;
    issue_stage(0, 0);
    if (nIter > 1) issue_stage(1, BK);
    if (nIter > 2) issue_stage(2, 2 * BK);

    for (int it = 0; it < nIter; it++) {
        CP_WAIT2();
        __syncthreads();
        if (it + 3 < nIter) issue_stage((it + 3) % STAGES, (it + 3) * BK);

        uint32_t Af = As_u + (it % STAGES) * A_ST_H * 2;
        uint32_t Bf = Bs_u + (it % STAGES) * B_ST_H * 2;

#pragma unroll
        for (int h = 0; h < 2; h++) {
            int kb = h * 16;
            uint32_t a[4][4];
#pragma unroll
            for (int mt = 0; mt < 4; mt++) {
                int rowa = wm * 64 + mt * 16 + lr8 + (lg & 1) * 8;
                int ka = kb + (lg >> 1) * 8;
                ldsm4(a[mt][0], a[mt][1], a[mt][2], a[mt][3],
                      Af + (rowa * ALDH + ka) * 2);
            }
            uint32_t b[4][2];
#pragma unroll
            for (int np = 0; np < 2; np++) {
                int rowb = wn * 32 + np * 16 + lr8 + (lg & 1) * 8;
                int kber = kb + (lg >> 1) * 8;
                uint32_t r0, r1, r2, r3;
                ldsm4(r0, r1, r2, r3, Bf + (rowb * BLDH + kber) * 2);
                b[np * 2 + 0][0] = r0; b[np * 2 + 0][1] = r2;
                b[np * 2 + 1][0] = r1; b[np * 2 + 1][1] = r3;
            }
#pragma unroll
            for (int mt = 0; mt < 4; mt++)
#pragma unroll
                for (int nt = 0; nt < 4; nt++) {
                    asm volatile(
                        "mma.sync.aligned.m16n8k16.row.col.f32.f16.f16.f32 "
                        "{%0,%1,%2,%3}, {%4,%5,%6,%7}, {%8,%9}, {%0,%1,%2,%3};"
                        : "+f"(acc[mt][nt][0]), "+f"(acc[mt][nt][1]),
                          "+f"(acc[mt][nt][2]), "+f"(acc[mt][nt][3])
                        : "r"(a[mt][0]), "r"(a[mt][1]), "r"(a[mt][2]), "r"(a[mt][3]),
                          "r"(b[nt][0]), "r"(b[nt][1]));
                }
        }
    }

    int lr = lane >> 2, lq = lane & 3;
    int odd = lane & 1;
#pragma unroll
    for (int mt = 0; mt < 4; mt++) {
        int rbase = wm * 64 + mt * 16 + lr;
        int o_lo = os[rbase];
        int o_hi = os[rbase + 8];
        int o = odd ? o_hi : o_lo;
#pragma unroll
        for (int nt = 0; nt < 4; nt++) {
            float e0 = __shfl_xor_sync(0xffffffffu, acc[mt][nt][0], 1);
            float e1 = __shfl_xor_sync(0xffffffffu, acc[mt][nt][1], 1);
            float e2 = __shfl_xor_sync(0xffffffffu, acc[mt][nt][2], 1);
            float e3 = __shfl_xor_sync(0xffffffffu, acc[mt][nt][3], 1);
            float v0, v1, v2, v3;
            if (!odd) { v0 = acc[mt][nt][0]; v1 = acc[mt][nt][1]; v2 = e0; v3 = e1; }
            else      { v0 = e2; v1 = e3; v2 = acc[mt][nt][2]; v3 = acc[mt][nt][3]; }
            int cb = col0 + wn * 32 + nt * 8 + (lq & 2) * 2;
            if (o >= 0) red4(&out[(long)o * 512 + cb], v0, v1, v2, v3);
        }
    }
}

// ---------------------------------------------------------------------------
// Center offset: identity map -> dense GEMM, coalesced v4 stores, initializes.
// ---------------------------------------------------------------------------
__global__ __launch_bounds__(256, 2)
void k_conv_center(const __half* __restrict__ x, const __half* __restrict__ W13,
                   int n, int K, float* __restrict__ out) {
    int row0 = blockIdx.x * BM;
    int col0 = blockIdx.y * BN;

    extern __shared__ __half smh[];
    int tid = threadIdx.x;
    int lrow = tid >> 1;
    int lseg = (tid & 1) * 16;
    int grow = row0 + lrow;
    const __half* xrow = (grow < n) ? &x[(long)grow * K] : nullptr;
    const __half* wcol = &W13[(long)(col0 + lrow) * K];

    uint32_t As_u = smem_u32(smh + AH_OFF);
    uint32_t Bs_u = smem_u32(smh + BH_OFF);

    auto issue_stage = [&](int stage, int k0) {
        uint32_t Ab = As_u + stage * A_ST_H * 2;
        uint32_t Bb = Bs_u + stage * B_ST_H * 2;
        const __half* asrc = xrow ? (xrow + k0 + lseg) : x;
        cp16(Ab + (lrow * ALDH + lseg) * 2,     asrc,     xrow != nullptr);
        cp16(Ab + (lrow * ALDH + lseg + 8) * 2, asrc + 8, xrow != nullptr);
        const __half* bsrc = wcol + k0 + lseg;
        cp16ca(Bb + (lrow * BLDH + lseg) * 2,     bsrc);
        cp16ca(Bb + (lrow * BLDH + lseg + 8) * 2, bsrc + 8);
        CP_COMMIT();
    };

    int warp = tid >> 5, lane = tid & 31;
    int wm = warp & 1, wn = warp >> 1;
    int lg = lane >> 3, lr8 = lane & 7;

    float acc[4][4][4];
#pragma unroll
    for (int mt = 0; mt < 4; mt++)
#pragma unroll
        for (int nt = 0; nt < 4; nt++)
#pragma unroll
            for (int i = 0; i < 4; i++) acc[mt][nt][i] = 0.0f;

    int nIter = K / BK;
    issue_stage(0, 0);
    if (nIter > 1) issue_stage(1, BK);
    if (nIter > 2) issue_stage(2, 2 * BK);

    for (int it = 0; it < nIter; it++) {
        CP_WAIT2();
        __syncthreads();
        if (it + 3 < nIter) issue_stage((it + 3) % STAGES, (it + 3) * BK);

        uint32_t Af = As_u + (it % STAGES) * A_ST_H * 2;
        uint32_t Bf = Bs_u + (it % STAGES) * B_ST_H * 2;

#pragma unroll
        for (int h = 0; h < 2; h++) {
            int kb = h * 16;
            uint32_t a[4][4];
#pragma unroll
            for (int mt = 0; mt < 4; mt++) {
                int rowa = wm * 64 + mt * 16 + lr8 + (lg & 1) * 8;
                int ka = kb + (lg >> 1) * 8;
                ldsm4(a[mt][0], a[mt][1], a[mt][2], a[mt][3],
                      Af + (rowa * ALDH + ka) * 2);
            }
            uint32_t b[4][2];
#pragma unroll
            for (int np = 0; np < 2; np++) {
                int rowb = wn * 32 + np * 16 + lr8 + (lg & 1) * 8;
                int kber = kb + (lg >> 1) * 8;
                uint32_t r0, r1, r2, r3;
                ldsm4(r0, r1, r2, r3, Bf + (rowb * BLDH + kber) * 2);
                b[np * 2 + 0][0] = r0; b[np * 2 + 0][1] = r2;
                b[np * 2 + 1][0] = r1; b[np * 2 + 1][1] = r3;
            }
#pragma unroll
            for (int mt = 0; mt < 4; mt++)
#pragma unroll
                for (int nt = 0; nt < 4; nt++) {
                    asm volatile(
                        "mma.sync.aligned.m16n8k16.row.col.f32.f16.f16.f32 "
                        "{%0,%1,%2,%3}, {%4,%5,%6,%7}, {%8,%9}, {%0,%1,%2,%3};"
                        : "+f"(acc[mt][nt][0]), "+f"(acc[mt][nt][1]),
                          "+f"(acc[mt][nt][2]), "+f"(acc[mt][nt][3])
                        : "r"(a[mt][0]), "r"(a[mt][1]), "r"(a[mt][2]), "r"(a[mt][3]),
                          "r"(b[nt][0]), "r"(b[nt][1]));
                }
        }
    }

    int lr = lane >> 2, lq = lane & 3;
    int odd = lane & 1;
#pragma unroll
    for (int mt = 0; mt < 4; mt++) {
        int r_lo = row0 + wm * 64 + mt * 16 + lr;
        int r = odd ? (r_lo + 8) : r_lo;
#pragma unroll
        for (int nt = 0; nt < 4; nt++) {
            float e0 = __shfl_xor_sync(0xffffffffu, acc[mt][nt][0], 1);
            float e1 = __shfl_xor_sync(0xffffffffu, acc[mt][nt][1], 1);
            float e2 = __shfl_xor_sync(0xffffffffu, acc[mt][nt][2], 1);
            float e3 = __shfl_xor_sync(0xffffffffu, acc[mt][nt][3], 1);
            float4 v;
            if (!odd) { v.x = acc[mt][nt][0]; v.y = acc[mt][nt][1]; v.z = e0; v.w = e1; }
            else      { v.x = e2; v.y = e3; v.z = acc[mt][nt][2]; v.w = acc[mt][nt][3]; }
            int cb = col0 + wn * 32 + nt * 8 + (lq & 2) * 2;
            if (r < n) *(float4*)&out[(long)r * 512 + cb] = v;
        }
    }
}

// ---------------------------------------------------------------------------
// BN stats + (last block) coef. g_sum/g_sumsq/g_done self-resetting.
// ---------------------------------------------------------------------------
__global__ void k_bn_stats(const float* __restrict__ x, int n,
                           const float* __restrict__ gamma,
                           const float* __restrict__ beta, float inv_n) {
    int c = threadIdx.x;
    int r0 = blockIdx.x * 128;
    int rend = min(r0 + 128, n);
    float s0 = 0.f, s20 = 0.f, s1 = 0.f, s21 = 0.f;
    for (int r = r0; r < rend; r++) {
        float v0 = x[(long)r * 512 + c];
        float v1 = x[(long)r * 512 + c + 256];
        s0 += v0; s20 += v0 * v0;
        s1 += v1; s21 += v1 * v1;
    }
    atomicAdd(&g_sum[c], s0);
    atomicAdd(&g_sumsq[c], s20);
    atomicAdd(&g_sum[c + 256], s1);
    atomicAdd(&g_sumsq[c + 256], s21);

    __threadfence();
    __shared__ int is_last;
    if (threadIdx.x == 0)
        is_last = (atomicAdd(&g_done, 1) == (int)gridDim.x - 1);
    __syncthreads();
    if (is_last) {
        __threadfence();
#pragma unroll
        for (int half = 0; half < 2; half++) {
            int ch = c + half * 256;
            float mu = g_sum[ch] * inv_n;
            float var = g_sumsq[ch] * inv_n - mu * mu;
            float a = gamma[ch] * rsqrtf(var + 1e-5f);
            g_coefA[ch] = a;
            g_coefB[ch] = beta[ch] - mu * a;
            g_sum[ch] = 0.0f;
            g_sumsq[ch] = 0.0f;
        }
        if (threadIdx.x == 0) g_done = 0;
    }
}

__global__ void k_bn_apply_h(const float* __restrict__ x, __half* __restrict__ y,
                             int total8) {
    int i = blockIdx.x * blockDim.x + threadIdx.x;
    int stride = gridDim.x * blockDim.x;
    for (; i < total8; i += stride) {
        float4 v0 = ((const float4*)x)[i * 2];
        float4 v1 = ((const float4*)x)[i * 2 + 1];
        int c = (i * 8) & 511;
        float4 a0 = *(const float4*)&g_coefA[c];
        float4 a1 = *(const float4*)&g_coefA[c + 4];
        float4 b0 = *(const float4*)&g_coefB[c];
        float4 b1 = *(const float4*)&g_coefB[c + 4];
        __half2 h[4];
        h[0] = __floats2half2_rn(fmaxf(v0.x * a0.x + b0.x, 0.f), fmaxf(v0.y * a0.y + b0.y, 0.f));
        h[1] = __floats2half2_rn(fmaxf(v0.z * a0.z + b0.z, 0.f), fmaxf(v0.w * a0.w + b0.w, 0.f));
        h[2] = __floats2half2_rn(fmaxf(v1.x * a1.x + b1.x, 0.f), fmaxf(v1.y * a1.y + b1.y, 0.f));
        h[3] = __floats2half2_rn(fmaxf(v1.z * a1.z + b1.z, 0.f), fmaxf(v1.w * a1.w + b1.w, 0.f));
        ((uint4*)y)[i] = *(const uint4*)h;
    }
}

// ---------------------------------------------------------------------------
// FC: 32 output cols x 8 K-slices per block.
// ---------------------------------------------------------------------------
__global__ __launch_bounds__(256)
void k_fc(const float* __restrict__ x, const float* __restrict__ w,
          const float* __restrict__ bias, float* __restrict__ y,
          int K, int N, int do_relu) {
    __shared__ float xs[8 * 512];
    __shared__ float red_[8][32][8];
    int tid = threadIdx.x;
    int cj = tid & 31, s = tid >> 5;
    int j = blockIdx.x * 32 + cj;
    bool jv = j < N;

    float acc[8];
#pragma unroll
    for (int b = 0; b < 8; b++) acc[b] = 0.f;

    for (int k0 = 0; k0 < K; k0 += 512) {
        for (int i = tid; i < 8 * 512; i += 256)
            xs[i] = x[(long)(i >> 9) * K + k0 + (i & 511)];
        __syncthreads();
        if (jv) {
            int kb = s * 64;
            for (int kk = kb; kk < kb + 64; kk++) {
                float wv = w[(long)(k0 + kk) * N + j];
#pragma unroll
                for (int b = 0; b < 8; b++) acc[b] += xs[b * 512 + kk] * wv;
            }
        }
        __syncthreads();
    }
#pragma unroll
    for (int b = 0; b < 8; b++) red_[s][cj][b] = acc[b];
    __syncthreads();
    if (s == 0 && jv) {
#pragma unroll
        for (int b = 0; b < 8; b++) {
            float v = bias[j];
#pragma unroll
            for (int t = 0; t < 8; t++) v += red_[t][cj][b];
            y[(long)b * N + j] = do_relu ? fmaxf(v, 0.f) : v;
        }
    }
}

// ---------------------------------------------------------------------------
extern "C" void kernel_launch(void* const* d_in, const int* in_sizes, int n_in,
                              void* d_out, int out_size) {
    const float* feats    = (const float*)d_in[0];
    const float* w[6]     = {(const float*)d_in[1], (const float*)d_in[2],
                             (const float*)d_in[3], (const float*)d_in[4],
                             (const float*)d_in[5], (const float*)d_in[6]};
    const float* bn_gamma = (const float*)d_in[7];
    const float* bn_beta  = (const float*)d_in[8];
    const float* fc1_w = (const float*)d_in[9];
    const float* fc1_b = (const float*)d_in[10];
    const float* fc2_w = (const float*)d_in[11];
    const float* fc2_b = (const float*)d_in[12];
    const float* fc3_w = (const float*)d_in[13];
    const float* fc3_b = (const float*)d_in[14];
    const int* map1_in  = (const int*)d_in[15];
    const int* map1_out = (const int*)d_in[16];
    const int* map2_in  = (const int*)d_in[17];
    const int* map2_out = (const int*)d_in[18];
    const int* pool1_idx = (const int*)d_in[19];
    const int* pool2_idx = (const int*)d_in[20];
    const int* batch_idx = (const int*)d_in[21];

    int n1 = in_sizes[19];
    int n2 = in_sizes[20];
    int n3 = in_sizes[21];
    int P1 = in_sizes[15] / 27;
    int P2 = in_sizes[17] / 27;
    (void)n3;

    float *acc, *glob, *fcb1, *fcb2;
    __half *hA, *hB, *wh;
    int *cnt1, *cnt2, *seg1, *ptr1, *inv1;
    cudaGetSymbolAddress((void**)&acc, g_acc);
    cudaGetSymbolAddress((void**)&hA, g_hA);
    cudaGetSymbolAddress((void**)&hB, g_hB);
    cudaGetSymbolAddress((void**)&wh, g_wh);
    cudaGetSymbolAddress((void**)&glob, g_glob);
    cudaGetSymbolAddress((void**)&fcb1, g_fcb1);
    cudaGetSymbolAddress((void**)&fcb2, g_fcb2);
    cudaGetSymbolAddress((void**)&cnt1, g_cnt1);
    cudaGetSymbolAddress((void**)&cnt2, g_cnt2);
    cudaGetSymbolAddress((void**)&seg1, g_seg1);
    cudaGetSymbolAddress((void**)&ptr1, g_ptr1);
    cudaGetSymbolAddress((void**)&inv1, g_inv1);

    static int smem_set = 0;
    if (!smem_set) {
        cudaFuncSetAttribute(k_conv_off,
                             cudaFuncAttributeMaxDynamicSharedMemorySize, SMEM_BYTES);
        cudaFuncSetAttribute(k_conv_center,
                             cudaFuncAttributeMaxDynamicSharedMemorySize, SMEM_BYTES);
        smem_set = 1;
    }

    long wofs[6];
    wofs[0] = 0;
    for (int l = 1; l < 6; l++)
        wofs[l] = wofs[l - 1] + (long)27 * 512 * (l == 1 ? 256 : 512);
    long wstride = (long)27 * 512 * 512;

    dim3 wtblk(32, 8);

    auto convC = [&](const __half* xin, const __half* Wc, int Kdim,
                     const int* m_in, const int* m_out, int* cnts, int P, int n) {
        dim3 gc((n + BM - 1) / BM, 512 / BN);
        k_conv_center<<<gc, 256, SMEM_BYTES>>>(xin, Wc + (long)13 * 512 * Kdim,
                                               n, Kdim, acc);
        dim3 go((P + BM - 1) / BM, 512 / BN, 26);
        k_conv_off<<<go, 256, SMEM_BYTES>>>(xin, Wc, m_in, m_out, cnts, P, Kdim,
                                            1, acc);
    };
    auto bn = [&](int n, int layer, __half* hout) {
        k_bn_stats<<<(n + 127) / 128, 256>>>(acc, n, bn_gamma + layer * 512,
                                             bn_beta + layer * 512,
                                             1.0f / (float)n);
        int total8 = n * 64;
        int blocks = min((total8 + 255) / 256, 8192);
        k_bn_apply_h<<<blocks, 256>>>(acc, hout, total8);
    };

    // ---- prologue ----
    cudaMemsetAsync(cnt1, 0, 27 * 4);
    cudaMemsetAsync(cnt2, 0, 27 * 4);
    cudaMemsetAsync(seg1, 0, (n2 + 1) * 4);
    k_wt<<<dim3(16, 256 / 32, 27), wtblk>>>(w[0], wh + wofs[0], 256);
    k_f2h<<<4096, 256>>>(feats, hA, n1 * 256);
    k_count_par<<<dim3(27, 8), 256>>>(map1_out, P1, n1, cnt1);

    // ---- conv1 (center first initializes acc; profiled slot) ----
    {
        dim3 gc((n1 + BM - 1) / BM, 512 / BN);
        k_conv_center<<<gc, 256, SMEM_BYTES>>>(hA, wh + wofs[0] + (long)13 * 512 * 256,
                                               n1, 256, acc);
    }
    k_count_par<<<dim3(27, 8), 256>>>(map2_out, P2, n2, cnt2);
    {
        dim3 go((P1 + BM - 1) / BM, 512 / BN, 26);
        k_conv_off<<<go, 256, SMEM_BYTES>>>(hA, wh + wofs[0], map1_in, map1_out,
                                            cnt1, P1, 256, 1, acc);
    }
    // overlapables: remaining weight converts + pool1 CSR build
    k_wt5<<<dim3(16, 16, 135), wtblk>>>(w[1], w[2], w[3], w[4], w[5],
                                        wh + wofs[1], wstride);
    k_hist<<<256, 256>>>(pool1_idx, n1, seg1);
    k_scan<<<1, 1024>>>(seg1, n2 + 1, ptr1);
    k_scatter<<<256, 256>>>(pool1_idx, n1, ptr1, inv1);
    bn(n1, 0, hB);

    convC(hB, wh + wofs[1], 512, map1_in, map1_out, cnt1, P1, n1); bn(n1, 1, hA);
    convC(hA, wh + wofs[2], 512, map1_in, map1_out, cnt1, P1, n1); bn(n1, 2, hB);

    // ---- pool1: CSR gather max, half -> half ----
    k_pool_csr<<<n2, 256>>>(hB, seg1, inv1, hA);

    // ---- level 2 ----
    convC(hA, wh + wofs[3], 512, map2_in, map2_out, cnt2, P2, n2); bn(n2, 3, hB);
    convC(hB, wh + wofs[4], 512, map2_in, map2_out, cnt2, P2, n2); bn(n2, 4, hA);
    convC(hA, wh + wofs[5], 512, map2_in, map2_out, cnt2, P2, n2); bn(n2, 5, hB);

    // ---- fused pool2 + global max (composed index) ----
    cudaMemsetAsync(glob, 0, 8 * 512 * 4);
    k_pool_compose<<<2048, 256>>>(hB, pool2_idx, batch_idx, glob, n2);

    // ---- FC head ----
    k_fc<<<128, 256>>>(glob, fc1_w, fc1_b, fcb1, 512, 4096, 1);
    k_fc<<<128, 256>>>(fcb1, fc2_w, fc2_b, fcb2, 4096, 4096, 1);
    k_fc<<<2, 256>>>(fcb2, fc3_w, fc3_b, (float*)d_out, 4096, 40, 0);
}